// round 6
// baseline (speedup 1.0000x reference)
#include <cuda_runtime.h>

#define NB    64
#define NV    4096
#define NFEAT 16
#define NA    8
#define NP    16
#define NOUT  16
#define S1    16                 // k1 splits per batch
#define CH    256                // vertices per k1 block
#define GRID1 (NB * S1)          // 1024
#define S2    8                  // k2 splits per batch
#define V2    (NV / S2)          // 512 vertices per k2 block
#define GRID2 (NB * S2)          // 512

// Per-(b,split) partials of sum_v ew[v,a]*feat[v,p]; slot owned exclusively.
__device__ float    g_part[GRID1 * 128];
// Per-batch M[a][n] produced by the fan-in block.
__device__ float    g_M[NB * 128];
// Per-vertex edge weights exported by k1 (valid vertices only).
__device__ float    g_ew[(size_t)NB * NV * NA];
// Per-batch monotonic arrival counters (never reset; mod-S1 epoch test).
__device__ unsigned g_cnt[NB];

// ---------------------------------------------------------------------------
// k1: per-block partial aggregation over 256 vertices + ew export + per-batch
//     fan-in (last arriving block reduces partials and computes M).
// ---------------------------------------------------------------------------
__global__ __launch_bounds__(256, 4) void k_aggregate(
    const float* __restrict__ data, const int* __restrict__ num_vertex,
    const float* __restrict__ W_flr, const float* __restrict__ b_flr,
    const float* __restrict__ W_s,   const float* __restrict__ b_s,
    const float* __restrict__ W_out)
{
    __shared__ float4 sWf4[NFEAT][4];
    __shared__ float4 sWs4[NFEAT][2];
    __shared__ float  sbf[NP];
    __shared__ float  sbs[NA];
    __shared__ float4 sStage[CH * 6];   // [0..3]=feat, [4..5]=ew per vertex
    __shared__ float  sFan[128];
    __shared__ unsigned sLast;

    const int t     = threadIdx.x;
    const int b     = blockIdx.x / S1;
    const int split = blockIdx.x % S1;
    const int nv    = num_vertex[b];
    const int vbase = split * CH;
    const bool work = (vbase < nv);     // block-uniform

    if (work) {
        if (t < 64) {
            sWf4[t >> 2][t & 3] = ((const float4*)W_flr)[t];
        } else if (t < 96) {
            const int u = t - 64;
            sWs4[u >> 1][u & 1] = ((const float4*)W_s)[u];
        } else if (t < 112) {
            sbf[t - 96] = b_flr[t - 96];
        } else if (t < 120) {
            sbs[t - 112] = b_s[t - 112];
        }
        __syncthreads();

        const int v = vbase + t;
        if (v < nv) {
            const float4* dp = (const float4*)(data + ((size_t)(b * NV + v)) * NFEAT);
            const float4 x0 = dp[0], x1 = dp[1], x2 = dp[2], x3 = dp[3];
            float x[16];
            x[0]=x0.x;  x[1]=x0.y;  x[2]=x0.z;  x[3]=x0.w;
            x[4]=x1.x;  x[5]=x1.y;  x[6]=x1.z;  x[7]=x1.w;
            x[8]=x2.x;  x[9]=x2.y;  x[10]=x2.z; x[11]=x2.w;
            x[12]=x3.x; x[13]=x3.y; x[14]=x3.z; x[15]=x3.w;

            #pragma unroll
            for (int g = 0; g < 4; ++g) {
                float s0 = sbf[g*4+0], s1 = sbf[g*4+1];
                float s2 = sbf[g*4+2], s3 = sbf[g*4+3];
                #pragma unroll
                for (int f = 0; f < 16; ++f) {
                    const float4 w = sWf4[f][g];
                    s0 += x[f]*w.x; s1 += x[f]*w.y;
                    s2 += x[f]*w.z; s3 += x[f]*w.w;
                }
                sStage[t*6 + g] = make_float4(s0, s1, s2, s3);
            }
            float4* ewp = (float4*)(g_ew + ((size_t)(b * NV + v)) * NA);
            #pragma unroll
            for (int g = 0; g < 2; ++g) {
                float s0 = sbs[g*4+0], s1 = sbs[g*4+1];
                float s2 = sbs[g*4+2], s3 = sbs[g*4+3];
                #pragma unroll
                for (int f = 0; f < 16; ++f) {
                    const float4 w = sWs4[f][g];
                    s0 += x[f]*w.x; s1 += x[f]*w.y;
                    s2 += x[f]*w.z; s3 += x[f]*w.w;
                }
                const float4 e = make_float4(__expf(-s0*s0), __expf(-s1*s1),
                                             __expf(-s2*s2), __expf(-s3*s3));
                sStage[t*6 + 4 + g] = e;
                ewp[g] = e;                    // export for k2 (coalesced 32B)
            }
        } else {
            const float4 z = make_float4(0.f, 0.f, 0.f, 0.f);
            #pragma unroll
            for (int g = 0; g < 6; ++g) sStage[t*6 + g] = z;
        }
        __syncthreads();

        // 32 owners (aa=o>>2, pg=o&3) x 8 slices of 32 vertices
        const int owner = t & 31;
        const int aa    = owner >> 2;
        const int pg    = owner & 3;
        const int slice = t >> 5;
        const float* sS = (const float*)sStage;
        float4 acc = make_float4(0.f, 0.f, 0.f, 0.f);

        const int v0 = slice * 32;
        #pragma unroll 4
        for (int i = 0; i < 32; ++i) {
            const int vv = v0 + i;
            const float  w = sS[vv*24 + 16 + aa];
            const float4 f = sStage[vv*6 + pg];
            acc.x += w * f.x; acc.y += w * f.y;
            acc.z += w * f.z; acc.w += w * f.w;
        }
        __syncthreads();

        float4* sRed = sStage;
        sRed[slice * 32 + owner] = acc;
        __syncthreads();
        if (t < 32) {
            float4 s = sRed[t];
            #pragma unroll
            for (int sl = 1; sl < 8; ++sl) {
                const float4 r = sRed[sl * 32 + t];
                s.x += r.x; s.y += r.y; s.z += r.z; s.w += r.w;
            }
            ((float4*)g_part)[blockIdx.x * 32 + t] = s;
            __threadfence();                 // release partials
        }
    } else {
        if (t < 32) {
            ((float4*)g_part)[blockIdx.x * 32 + t] = make_float4(0.f, 0.f, 0.f, 0.f);
            __threadfence();
        }
    }
    __syncthreads();

    // ---- per-batch fan-in: last arrival reduces partials and computes M ----
    if (t == 0) {
        const unsigned old = atomicAdd(&g_cnt[b], 1u);
        sLast = ((old & (S1 - 1)) == (S1 - 1)) ? 1u : 0u;
    }
    __syncthreads();
    if (sLast) {
        __threadfence();                     // acquire partials
        if (t < 32) {
            float4 s = make_float4(0.f, 0.f, 0.f, 0.f);
            #pragma unroll
            for (int sp = 0; sp < S1; ++sp) {
                const float4 r = ((const float4*)g_part)[(b * S1 + sp) * 32 + t];
                s.x += r.x; s.y += r.y; s.z += r.z; s.w += r.w;
            }
            const float inv = 1.0f / (float)NV;
            s.x *= inv; s.y *= inv; s.z *= inv; s.w *= inv;
            ((float4*)sFan)[t] = s;          // agg[a*16+p]
        }
        __syncthreads();
        if (t < 128) {
            const int a = t >> 4, n = t & 15;
            float m = 0.f;
            #pragma unroll
            for (int p = 0; p < NP; ++p)
                m += sFan[a*NP + p] * W_out[(a*NP + p)*NOUT + n];
            g_M[b * 128 + t] = m;            // cross-kernel visibility via launch edge
        }
    }
}

// ---------------------------------------------------------------------------
// k2: out[b,v,:] = mask * (sum_a ew[v,a]*M[a,:] + b_out). 2 vertices/thread.
// ---------------------------------------------------------------------------
__global__ __launch_bounds__(256, 4) void k_output(
    const int* __restrict__ num_vertex, const float* __restrict__ b_out,
    float* __restrict__ out)
{
    __shared__ __align__(16) float sM[128];
    __shared__ float sbo[NOUT];

    const int t  = threadIdx.x;
    const int b  = blockIdx.x / S2;
    const int vb = (blockIdx.x % S2) * V2;
    const int nv = num_vertex[b];
    const float4 z = make_float4(0.f, 0.f, 0.f, 0.f);

    if (vb >= nv) {                          // fully masked: zero-fill 512 vertices
        #pragma unroll
        for (int s = 0; s < 2; ++s) {
            float4* op = (float4*)(out + ((size_t)(b * NV + vb + s*256 + t)) * NOUT);
            op[0] = z; op[1] = z; op[2] = z; op[3] = z;
        }
        return;
    }

    if (t < 32) {
        ((float4*)sM)[t] = ((const float4*)g_M)[b * 32 + t];
    } else if (t < 48) {
        sbo[t - 32] = b_out[t - 32];
    }
    __syncthreads();

    const int v0 = vb + t, v1 = vb + 256 + t;
    const bool val0 = (v0 < nv), val1 = (v1 < nv);

    float4 e00 = z, e01 = z, e10 = z, e11 = z;
    if (val0) {
        const float4* ep = (const float4*)(g_ew + ((size_t)(b * NV + v0)) * NA);
        e00 = ep[0]; e01 = ep[1];
    }
    if (val1) {
        const float4* ep = (const float4*)(g_ew + ((size_t)(b * NV + v1)) * NA);
        e10 = ep[0]; e11 = ep[1];
    }
    float ew0[8] = {e00.x, e00.y, e00.z, e00.w, e01.x, e01.y, e01.z, e01.w};
    float ew1[8] = {e10.x, e10.y, e10.z, e10.w, e11.x, e11.y, e11.z, e11.w};

    float4 o0[4], o1[4];
    #pragma unroll
    for (int j = 0; j < 4; ++j) {
        o0[j] = make_float4(sbo[j*4], sbo[j*4+1], sbo[j*4+2], sbo[j*4+3]);
        o1[j] = o0[j];
    }
    #pragma unroll
    for (int a = 0; a < NA; ++a) {
        const float w0 = ew0[a], w1 = ew1[a];
        const float4* mrow = (const float4*)(sM + a * NOUT);
        #pragma unroll
        for (int j = 0; j < 4; ++j) {
            const float4 m = mrow[j];      // one LDS.128 shared by both vertices
            o0[j].x += w0 * m.x; o0[j].y += w0 * m.y;
            o0[j].z += w0 * m.z; o0[j].w += w0 * m.w;
            o1[j].x += w1 * m.x; o1[j].y += w1 * m.y;
            o1[j].z += w1 * m.z; o1[j].w += w1 * m.w;
        }
    }

    float4* op0 = (float4*)(out + ((size_t)(b * NV + v0)) * NOUT);
    float4* op1 = (float4*)(out + ((size_t)(b * NV + v1)) * NOUT);
    if (val0) { op0[0]=o0[0]; op0[1]=o0[1]; op0[2]=o0[2]; op0[3]=o0[3]; }
    else      { op0[0]=z;     op0[1]=z;     op0[2]=z;     op0[3]=z;     }
    if (val1) { op1[0]=o1[0]; op1[1]=o1[1]; op1[2]=o1[2]; op1[3]=o1[3]; }
    else      { op1[0]=z;     op1[1]=z;     op1[2]=z;     op1[3]=z;     }
}

extern "C" void kernel_launch(void* const* d_in, const int* in_sizes, int n_in,
                              void* d_out, int out_size) {
    const float* data       = (const float*)d_in[0];
    const int*   num_vertex = (const int*)  d_in[1];
    const float* W_flr      = (const float*)d_in[2];
    const float* b_flr      = (const float*)d_in[3];
    const float* W_s        = (const float*)d_in[4];
    const float* b_s        = (const float*)d_in[5];
    const float* W_out      = (const float*)d_in[6];
    const float* b_out      = (const float*)d_in[7];
    float* out = (float*)d_out;

    k_aggregate<<<GRID1, 256>>>(data, num_vertex, W_flr, b_flr, W_s, b_s, W_out);
    k_output<<<GRID2, 256>>>(num_vertex, b_out, out);
}